// round 14
// baseline (speedup 1.0000x reference)
#include <cuda_runtime.h>
#include <math.h>

#define SS 8
#define DD 64
#define KK 512
#define NTOK 16384
#define TPB 64
#define HC 64                     // codes per half-chunk
#define NHC 8                     // half-chunks per slot
#define NTILE (NTOK/TPB)          // 256
#define ZQ_OFF 0
#define ZE_OFF (NTOK*DD)          // 1048576
#define ZK_OFF (2*NTOK*DD)        // 2097152

typedef unsigned long long ULL;

// one record per half-chunk: 16KB packed E + 256B norms = 16640 B
struct __align__(16) ERec {
    float4 data[1024];   // [d][q]: float4 = codes (4q..4q+3) at dim d
    float  En[HC];
};
__device__ ERec g_Erec[SS*NHC];
// per-slot z scratch: [s][token][d]  (32 MB)
__device__ __align__(16) float g_z[(size_t)SS*NTOK*DD];
// per-tile arrival counters (zero-init; winner resets -> invariant across replays)
__device__ int g_cnt[NTILE];

__device__ __forceinline__ void fma2(ULL& d, ULL a, ULL b) {
    asm("fma.rn.f32x2 %0, %1, %2, %3;" : "=l"(d) : "l"(a), "l"(b), "l"(d));
}
__device__ __forceinline__ float2 unpk(ULL v) {
    float lo, hi;
    asm("mov.b64 {%0,%1}, %2;" : "=f"(lo), "=f"(hi) : "l"(v));
    return make_float2(lo, hi);
}
__device__ __forceinline__ ULL dup2(float v) {
    ULL r; asm("mov.b64 %0, {%1, %1};" : "=l"(r) : "f"(v)); return r;
}
__device__ __forceinline__ void cp16(void* sdst, const void* gsrc) {
    unsigned sa = (unsigned)__cvta_generic_to_shared(sdst);
    asm volatile("cp.async.cg.shared.global [%0], [%1], 16;" :: "r"(sa), "l"(gsrc));
}
#define CP_COMMIT() asm volatile("cp.async.commit_group;")
#define CP_WAIT(n)  asm volatile("cp.async.wait_group %0;" :: "n"(n))

// ---- merged prep: blocks [0,64) transpose-pack one half-chunk each; [64,80) norms ----
__global__ __launch_bounds__(256)
void prep_kernel(const float* __restrict__ E) {
    if (blockIdx.x < SS*NHC) {
        __shared__ float tile[HC][DD+1];      // 16640 B, padded
        const int b = blockIdx.x;             // s*8 + hc
        const float4* src = (const float4*)(E + (size_t)b * HC * DD);
        for (int i = threadIdx.x; i < HC*16; i += 256) {
            int row = i >> 4, f4 = i & 15;
            float4 v = src[row*16 + f4];
            tile[row][f4*4+0] = v.x; tile[row][f4*4+1] = v.y;
            tile[row][f4*4+2] = v.z; tile[row][f4*4+3] = v.w;
        }
        __syncthreads();
        for (int j = threadIdx.x; j < 1024; j += 256) {
            int q = j & 15, d = j >> 4;
            g_Erec[b].data[d*16 + q] =
                make_float4(tile[4*q+0][d], tile[4*q+1][d], tile[4*q+2][d], tile[4*q+3][d]);
        }
    } else {
        // norms: sequential d-order rounding (reference-matched)
        int row = (blockIdx.x - SS*NHC) * 256 + threadIdx.x;   // s*KK + k, < 4096
        const float* e = E + (size_t)row * DD;
        float4 v[16];
        #pragma unroll
        for (int j = 0; j < 16; ++j) v[j] = *(const float4*)(e + 4*j);
        float s = 0.f;
        #pragma unroll
        for (int j = 0; j < 16; ++j) {
            s = __fadd_rn(s, __fmul_rn(v[j].x, v[j].x));
            s = __fadd_rn(s, __fmul_rn(v[j].y, v[j].y));
            s = __fadd_rn(s, __fmul_rn(v[j].z, v[j].z));
            s = __fadd_rn(s, __fmul_rn(v[j].w, v[j].w));
        }
        g_Erec[row >> 6].En[row & 63] = s;
    }
}

// smem layout (101440 B), 2 CTAs/SM:
//  +0      z_nd  [64][68] = 17408   (live through dist)
//  +17408  x_nd  [64][68] = 17408 \  dead after softmax;
//  +34816  W_sm  [64][64] = 16384 /  B2 @17408 (16640), B3 @34048 (16640) overlay
//  +51200  att   [64][65] = 16640    (dead after softmax)
//  +67840  B0 16640 | +84480 B1 16640   (dedicated; prefetched at kernel start)
//  +101120 znorm 256 | +101376 last_flag
#define B0_OFF 67840
#define B1_OFF 84480
#define B2_OFF 17408
#define B3_OFF 34048
#define SMEM_BYTES 101440

// one pass over a pair of half-chunk buffers: codes cb..cb+127; token-pair f32x2
__device__ __forceinline__ void dist_pass(
    const float* __restrict__ zb,             // &z_nd[0][w*8]
    const char* BA, const char* BB,
    const float* __restrict__ znorm,
    int w, int l, int cb, float* best_v, int* best_i)
{
    const int li = l & 15;
    const float4* ep  = ((l < 16) ? (const float4*)BA : (const float4*)BB) + li;
    const float*  enp = ((l < 16) ? (const float*)(BA + 16384)
                                  : (const float*)(BB + 16384)) + 4*li;
    const int cbase = cb + ((l >> 4) << 6) + 4*li;

    ULL acc[4][4];
    #pragma unroll
    for (int p = 0; p < 4; ++p)
        #pragma unroll
        for (int c = 0; c < 4; ++c) acc[p][c] = 0ull;

    #pragma unroll 8
    for (int d = 0; d < DD; ++d) {
        ulonglong2 za = *(const ulonglong2*)(zb + d*68);       // (z0,z1),(z2,z3)
        ulonglong2 zc = *(const ulonglong2*)(zb + d*68 + 4);   // (z4,z5),(z6,z7)
        float4 ea = ep[d*16];
        ULL e0 = dup2(ea.x), e1 = dup2(ea.y), e2 = dup2(ea.z), e3 = dup2(ea.w);
        fma2(acc[0][0], za.x, e0); fma2(acc[1][0], za.y, e0);
        fma2(acc[2][0], zc.x, e0); fma2(acc[3][0], zc.y, e0);
        fma2(acc[0][1], za.x, e1); fma2(acc[1][1], za.y, e1);
        fma2(acc[2][1], zc.x, e1); fma2(acc[3][1], zc.y, e1);
        fma2(acc[0][2], za.x, e2); fma2(acc[1][2], za.y, e2);
        fma2(acc[2][2], zc.x, e2); fma2(acc[3][2], zc.y, e2);
        fma2(acc[0][3], za.x, e3); fma2(acc[1][3], za.y, e3);
        fma2(acc[2][3], zc.x, e3); fma2(acc[3][3], zc.y, e3);
    }

    float4 en = *(const float4*)enp;
    const float en_[4] = {en.x, en.y, en.z, en.w};
    #pragma unroll
    for (int p = 0; p < 4; ++p) {
        float zn0 = znorm[w*8 + 2*p];
        float zn1 = znorm[w*8 + 2*p + 1];
        #pragma unroll
        for (int c = 0; c < 4; ++c) {
            float2 dd = unpk(acc[p][c]);
            int code = cbase + c;
            // (zn - 2*dot) + En ; fma(-2,dot,zn) == fsub(zn,2*dot) since 2*dot exact
            float v0 = __fadd_rn(__fmaf_rn(-2.f, dd.x, zn0), en_[c]);
            float v1 = __fadd_rn(__fmaf_rn(-2.f, dd.y, zn1), en_[c]);
            if (v0 < best_v[2*p])   { best_v[2*p]   = v0; best_i[2*p]   = code; }
            if (v1 < best_v[2*p+1]) { best_v[2*p+1] = v1; best_i[2*p+1] = code; }
        }
    }
}

__global__ __launch_bounds__(256, 2)
void qlayer_k1(const float* __restrict__ x,
               const float* __restrict__ W,
               const float* __restrict__ bias,
               const float* __restrict__ gamma,
               const float* __restrict__ beta,
               const float* __restrict__ bn_mean,
               const float* __restrict__ bn_var,
               const float* __restrict__ E,
               float* __restrict__ out)
{
    extern __shared__ char smraw[];
    float (*z_nd)[68]   = (float(*)[68])smraw;
    float (*x_nd)[68]   = (float(*)[68])(smraw + 17408);
    float (*W_sm)[DD]   = (float(*)[DD])(smraw + 34816);
    float (*att)[DD+1]  = (float(*)[DD+1])(smraw + 51200);
    float* znorm = (float*)(smraw + 101120);
    int*   lastf = (int*)(smraw + 101376);

    const int tid  = threadIdx.x;
    const int tok0 = blockIdx.x * TPB;
    const int s    = blockIdx.y;

    const ERec* esrc = g_Erec + s*NHC;

    // copy two half-chunk records (1040 float4 each incl. norms), one commit group
    #define ISSUE2(hA, hB, BA, BB) do {                                     \
        const float4* _sA = (const float4*)(esrc + (hA));                   \
        const float4* _sB = (const float4*)(esrc + (hB));                   \
        float4* _dA = (float4*)(smraw + (BA));                              \
        float4* _dB = (float4*)(smraw + (BB));                              \
        for (int _i = tid; _i < 1040; _i += 256) {                          \
            cp16(&_dA[_i], &_sA[_i]);                                       \
            cp16(&_dB[_i], &_sB[_i]);                                       \
        }                                                                   \
        CP_COMMIT();                                                        \
    } while (0)

    // group 1: half-chunks 0,1 into dedicated buffers (hidden under proj+softmax)
    ISSUE2(0, 1, B0_OFF, B1_OFF);

    // ---- load x tile transposed (non-dup); W in parallel ----
    {
        const int t = tid & 63, dg = tid >> 6;
        const float* xp = x + (size_t)(tok0 + t) * DD + dg * 16;
        #pragma unroll
        for (int j = 0; j < 4; ++j) {
            float4 v = *(const float4*)(xp + j * 4);
            int d = dg * 16 + j * 4;
            x_nd[d+0][t] = v.x; x_nd[d+1][t] = v.y;
            x_nd[d+2][t] = v.z; x_nd[d+3][t] = v.w;
        }
    }
    for (int i = tid; i < DD*DD; i += 256)
        ((float*)W_sm)[i] = W[s*DD*DD + i];
    __syncthreads();

    // ---- proj GEMM (f32x2 token-pairs): 4 tokens x 4 e per thread ----
    {
        const int ty = tid >> 4, tx = tid & 15;
        ULL acc[2][4];
        #pragma unroll
        for (int p = 0; p < 2; ++p)
            #pragma unroll
            for (int e = 0; e < 4; ++e) acc[p][e] = 0ull;
        #pragma unroll 8
        for (int d = 0; d < DD; ++d) {
            ulonglong2 xu = *(const ulonglong2*)&x_nd[d][ty*4];   // (x0,x1),(x2,x3)
            float4 wv = *(const float4*)&W_sm[d][tx*4];
            ULL w0 = dup2(wv.x), w1 = dup2(wv.y), w2 = dup2(wv.z), w3 = dup2(wv.w);
            fma2(acc[0][0], xu.x, w0); fma2(acc[1][0], xu.y, w0);
            fma2(acc[0][1], xu.x, w1); fma2(acc[1][1], xu.y, w1);
            fma2(acc[0][2], xu.x, w2); fma2(acc[1][2], xu.y, w2);
            fma2(acc[0][3], xu.x, w3); fma2(acc[1][3], xu.y, w3);
        }
        // BN, reference op order
        float4 bi4 = *(const float4*)&bias[s*DD + tx*4];
        float4 gm4 = *(const float4*)&gamma[s*DD + tx*4];
        float4 bt4 = *(const float4*)&beta[s*DD + tx*4];
        float4 mn4 = *(const float4*)&bn_mean[s*DD + tx*4];
        float4 vr4 = *(const float4*)&bn_var[s*DD + tx*4];
        const float bi_[4] = {bi4.x, bi4.y, bi4.z, bi4.w};
        const float gm_[4] = {gm4.x, gm4.y, gm4.z, gm4.w};
        const float bt_[4] = {bt4.x, bt4.y, bt4.z, bt4.w};
        const float mn_[4] = {mn4.x, mn4.y, mn4.z, mn4.w};
        float iv_[4];
        iv_[0] = 1.0f / sqrtf(__fadd_rn(vr4.x, 1e-3f));
        iv_[1] = 1.0f / sqrtf(__fadd_rn(vr4.y, 1e-3f));
        iv_[2] = 1.0f / sqrtf(__fadd_rn(vr4.z, 1e-3f));
        iv_[3] = 1.0f / sqrtf(__fadd_rn(vr4.w, 1e-3f));
        #pragma unroll
        for (int p = 0; p < 2; ++p) {
            #pragma unroll
            for (int e = 0; e < 4; ++e) {
                float2 pr = unpk(acc[p][e]);
                float pv = __fadd_rn(pr.x, bi_[e]);
                att[ty*4+2*p][tx*4+e] =
                    __fadd_rn(__fmul_rn(__fmul_rn(gm_[e], __fsub_rn(pv, mn_[e])), iv_[e]), bt_[e]);
                pv = __fadd_rn(pr.y, bi_[e]);
                att[ty*4+2*p+1][tx*4+e] =
                    __fadd_rn(__fmul_rn(__fmul_rn(gm_[e], __fsub_rn(pv, mn_[e])), iv_[e]), bt_[e]);
            }
        }
    }
    __syncthreads();

    // ---- softmax + z (4 threads/token), write z to smem (non-dup) + scratch ----
    {
        const int t = tid >> 2, q = tid & 3;
        float ev[16];
        float m = -INFINITY;
        #pragma unroll
        for (int j = 0; j < 16; ++j) { ev[j] = att[t][q*16 + j]; m = fmaxf(m, ev[j]); }
        m = fmaxf(m, __shfl_xor_sync(0xffffffffu, m, 1));
        m = fmaxf(m, __shfl_xor_sync(0xffffffffu, m, 2));
        float sum = 0.f;
        #pragma unroll
        for (int j = 0; j < 16; ++j) { ev[j] = expf(ev[j] - m); sum = __fadd_rn(sum, ev[j]); }
        sum = __fadd_rn(sum, __shfl_xor_sync(0xffffffffu, sum, 1));
        sum = __fadd_rn(sum, __shfl_xor_sync(0xffffffffu, sum, 2));
        float inv = __fdiv_rn(1.0f, sum);
        float zn = 0.f;
        float zv[16];
        #pragma unroll
        for (int j = 0; j < 16; ++j) {
            float a = __fmul_rn(ev[j], inv);
            float xx = x_nd[q*16 + j][t];
            float z = __fmul_rn(xx, a);
            zv[j] = z;
            z_nd[q*16 + j][t] = z;
            zn = __fadd_rn(zn, __fmul_rn(z, z));
        }
        float* zp = g_z + ((size_t)s*NTOK + tok0 + t) * DD + q*16;
        #pragma unroll
        for (int j4 = 0; j4 < 4; ++j4)
            *(float4*)(zp + 4*j4) = make_float4(zv[4*j4], zv[4*j4+1], zv[4*j4+2], zv[4*j4+3]);
        zn = __fadd_rn(zn, __shfl_xor_sync(0xffffffffu, zn, 1));
        zn = __fadd_rn(zn, __shfl_xor_sync(0xffffffffu, zn, 2));
        if (q == 0) znorm[t] = zn;
    }
    __syncthreads();    // z ready; x/W/att dead -> overlay buffers usable

    // ---- codebook distance: 4 pipelined passes over half-chunk pairs ----
    const int w = tid >> 5, l = tid & 31;
    const float* zb = &z_nd[0][w*8];
    float best_v[8]; int best_i[8];
    #pragma unroll
    for (int i = 0; i < 8; ++i) { best_v[i] = INFINITY; best_i[i] = 0x7fffffff; }

    ISSUE2(2, 3, B2_OFF, B3_OFF);       // group 2 (completes during pass 1)
    CP_WAIT(1); __syncthreads();        // group 1 ready
    dist_pass(zb, smraw + B0_OFF, smraw + B1_OFF, znorm, w, l, 0*2*HC, best_v, best_i);
    __syncthreads();

    ISSUE2(4, 5, B0_OFF, B1_OFF);       // group 3 (completes during pass 2)
    CP_WAIT(1); __syncthreads();        // group 2 ready
    dist_pass(zb, smraw + B2_OFF, smraw + B3_OFF, znorm, w, l, 1*2*HC, best_v, best_i);
    __syncthreads();

    ISSUE2(6, 7, B2_OFF, B3_OFF);       // group 4 (completes during pass 3)
    CP_WAIT(1); __syncthreads();        // group 3 ready
    dist_pass(zb, smraw + B0_OFF, smraw + B1_OFF, znorm, w, l, 2*2*HC, best_v, best_i);
    __syncthreads();

    CP_WAIT(0); __syncthreads();        // group 4 ready
    dist_pass(zb, smraw + B2_OFF, smraw + B3_OFF, znorm, w, l, 3*2*HC, best_v, best_i);
    #undef ISSUE2

    // ---- warp argmin reduction (first-occurrence => min index tie-break) ----
    #pragma unroll
    for (int i = 0; i < 8; ++i) {
        float v = best_v[i]; int bi = best_i[i];
        #pragma unroll
        for (int off = 16; off > 0; off >>= 1) {
            float ov = __shfl_xor_sync(0xffffffffu, v, off);
            int   oi = __shfl_xor_sync(0xffffffffu, bi, off);
            if (ov < v || (ov == v && oi < bi)) { v = ov; bi = oi; }
        }
        if (l == i)
            out[ZK_OFF + (size_t)s*NTOK + tok0 + w*8 + i] = (float)bi;
    }

    // ---- fused tail: 8th CTA of this tile reduces z_e / z_q (fixed s-order) ----
    __syncthreads();
    if (tid == 0) {
        __threadfence();
        int old = atomicAdd(&g_cnt[blockIdx.x], 1);
        *lastf = (old == SS-1);
    }
    __syncthreads();
    if (*lastf) {
        __threadfence();   // acquire: all 8 CTAs' g_z / zk writes visible
        const int t = tid >> 2, q = tid & 3;   // local token, quarter
        const int T = tok0 + t;
        float ae[16], aq[16];
        #pragma unroll
        for (int j = 0; j < 16; ++j) { ae[j] = 0.f; aq[j] = 0.f; }
        #pragma unroll
        for (int ss = 0; ss < SS; ++ss) {
            const float* zp = g_z + ((size_t)ss*NTOK + T) * DD + q*16;
            #pragma unroll
            for (int j4 = 0; j4 < 4; ++j4) {
                float4 v = *(const float4*)(zp + 4*j4);
                ae[4*j4+0] = __fadd_rn(ae[4*j4+0], v.x);
                ae[4*j4+1] = __fadd_rn(ae[4*j4+1], v.y);
                ae[4*j4+2] = __fadd_rn(ae[4*j4+2], v.z);
                ae[4*j4+3] = __fadd_rn(ae[4*j4+3], v.w);
            }
            const int k = (int)out[ZK_OFF + (size_t)ss*NTOK + T];
            const float* ep = E + ((size_t)ss*KK + k) * DD + q*16;
            #pragma unroll
            for (int j4 = 0; j4 < 4; ++j4) {
                float4 v = *(const float4*)(ep + 4*j4);
                aq[4*j4+0] = __fadd_rn(aq[4*j4+0], v.x);
                aq[4*j4+1] = __fadd_rn(aq[4*j4+1], v.y);
                aq[4*j4+2] = __fadd_rn(aq[4*j4+2], v.z);
                aq[4*j4+3] = __fadd_rn(aq[4*j4+3], v.w);
            }
        }
        float* oq = out + ZQ_OFF + (size_t)T * DD + q*16;
        float* oe = out + ZE_OFF + (size_t)T * DD + q*16;
        #pragma unroll
        for (int j4 = 0; j4 < 4; ++j4) {
            *(float4*)(oq + 4*j4) = make_float4(aq[4*j4], aq[4*j4+1], aq[4*j4+2], aq[4*j4+3]);
            *(float4*)(oe + 4*j4) = make_float4(ae[4*j4], ae[4*j4+1], ae[4*j4+2], ae[4*j4+3]);
        }
        if (tid == 0) g_cnt[blockIdx.x] = 0;   // reset for next graph replay
    }
}

// fillers so k1 lands at absolute launch index 5 for ncu (-s 5 -c 1):
// 2 harness launches precede; cycle = prep(2),noopA(3),noopB(4),k1(5)
__global__ void noopA_kernel() {}
__global__ void noopB_kernel() {}

extern "C" void kernel_launch(void* const* d_in, const int* in_sizes, int n_in,
                              void* d_out, int out_size)
{
    const float* x       = (const float*)d_in[0];
    const float* W       = (const float*)d_in[1];
    const float* b       = (const float*)d_in[2];
    const float* gamma   = (const float*)d_in[3];
    const float* beta    = (const float*)d_in[4];
    const float* bn_mean = (const float*)d_in[5];
    const float* bn_var  = (const float*)d_in[6];
    const float* E       = (const float*)d_in[7];
    float* out = (float*)d_out;

    prep_kernel<<<SS*NHC + 16, 256>>>(E);
    noopA_kernel<<<1, 32>>>();
    noopB_kernel<<<1, 32>>>();

    cudaFuncSetAttribute(qlayer_k1,
                         cudaFuncAttributeMaxDynamicSharedMemorySize, SMEM_BYTES);
    qlayer_k1<<<dim3(NTILE, SS), 256, SMEM_BYTES>>>(x, W, b, gamma, beta,
                                                    bn_mean, bn_var, E, out);
}

// round 15
// speedup vs baseline: 1.0455x; 1.0455x over previous
#include <cuda_runtime.h>
#include <math.h>

#define SS 8
#define DD 64
#define KK 512
#define NTOK 16384
#define TPB 64
#define CHUNK 128
#define NCHUNK 4
#define NTILE (NTOK/TPB)          // 256
#define ZQ_OFF 0
#define ZE_OFF (NTOK*DD)          // 1048576
#define ZK_OFF (2*NTOK*DD)        // 2097152

typedef unsigned long long ULL;

__device__ float g_Enorm[SS*KK];
// lane-quad pack: [s][c][d][q], float4 = codes (c*128+4q .. +3) at dim d
__device__ __align__(16) float4 g_Epack4[SS*NCHUNK*DD*32];
// per-slot z scratch: [s][token][d]  (32 MB)
__device__ __align__(16) float g_z[(size_t)SS*NTOK*DD];
// per-tile arrival counters (zero-init; winner resets -> invariant across replays)
__device__ int g_cnt[NTILE];

__device__ __forceinline__ void fma2(ULL& d, ULL a, ULL b) {
    asm("fma.rn.f32x2 %0, %1, %2, %3;" : "=l"(d) : "l"(a), "l"(b), "l"(d));
}
__device__ __forceinline__ float2 unpk(ULL v) {
    float lo, hi;
    asm("mov.b64 {%0,%1}, %2;" : "=f"(lo), "=f"(hi) : "l"(v));
    return make_float2(lo, hi);
}
__device__ __forceinline__ ULL dup2(float v) {
    ULL r; asm("mov.b64 %0, {%1, %1};" : "=l"(r) : "f"(v)); return r;
}
__device__ __forceinline__ void cp16(void* sdst, const void* gsrc) {
    unsigned sa = (unsigned)__cvta_generic_to_shared(sdst);
    asm volatile("cp.async.cg.shared.global [%0], [%1], 16;" :: "r"(sa), "l"(gsrc));
}
#define CP_COMMIT() asm volatile("cp.async.commit_group;")
#define CP_WAIT(n)  asm volatile("cp.async.wait_group %0;" :: "n"(n))

// ---- merged prep: blocks [0,128) transpose-pack; [128,144) norms ----
__global__ __launch_bounds__(256)
void prep_kernel(const float* __restrict__ E) {
    if (blockIdx.x < SS*NCHUNK*4) {
        __shared__ float tile[32][DD];        // 8 KB
        const int b   = blockIdx.x >> 2;      // chunk id: s*4 + c
        const int sub = blockIdx.x & 3;       // rows [sub*32, sub*32+32)
        const float* base = E + ((size_t)b * CHUNK + sub*32) * DD;
        for (int i = threadIdx.x; i < 32*DD/4; i += 256) {
            int row = i >> 4, f4 = i & 15;
            float4 v = *(const float4*)(base + row*DD + f4*4);
            tile[row][f4*4+0] = v.x; tile[row][f4*4+1] = v.y;
            tile[row][f4*4+2] = v.z; tile[row][f4*4+3] = v.w;
        }
        __syncthreads();
        for (int j = threadIdx.x; j < DD*8; j += 256) {
            int ql = j & 7, d = j >> 3;
            int lr = 4*ql;
            g_Epack4[b*2048 + d*32 + sub*8 + ql] =
                make_float4(tile[lr+0][d], tile[lr+1][d], tile[lr+2][d], tile[lr+3][d]);
        }
    } else {
        // norms: sequential d-order rounding (reference-matched)
        int row = (blockIdx.x - SS*NCHUNK*4) * 256 + threadIdx.x;   // < 4096
        const float* e = E + (size_t)row * DD;
        float4 v[16];
        #pragma unroll
        for (int j = 0; j < 16; ++j) v[j] = *(const float4*)(e + 4*j);
        float s = 0.f;
        #pragma unroll
        for (int j = 0; j < 16; ++j) {
            s = __fadd_rn(s, __fmul_rn(v[j].x, v[j].x));
            s = __fadd_rn(s, __fmul_rn(v[j].y, v[j].y));
            s = __fadd_rn(s, __fmul_rn(v[j].z, v[j].z));
            s = __fadd_rn(s, __fmul_rn(v[j].w, v[j].w));
        }
        g_Enorm[row] = s;
    }
}

// smem layout (102016 B), 2 CTAs/SM:
//  +0      z_nd  [64][68] = 17408   (live through dist)
//  +17408  x_nd  [64][68] = 17408 \  dead after softmax;
//  +34816  W_sm  [64][64] = 16384 /  EB (32768) overlays x_nd+W
//  +51200  att   [64][65] = 16640    (dead after softmax)
//  +67840  EA 32768 (dedicated; prefetched at kernel start)
//  +100608 EnA 512 | +101120 EnB 512 | +101632 znorm 256 | +101888 last_flag
#define SMEM_BYTES 102016

// two chunks per pass: codes cbA+4l..+3 (EA) and cbB+4l..+3 (EB); token-pair f32x2
__device__ __forceinline__ void dist_pair(
    const float* __restrict__ zb,             // &z_nd[0][w*8]
    const float4* __restrict__ EA, const float4* __restrict__ EB,
    const float* __restrict__ EnA, const float* __restrict__ EnB,
    const float* __restrict__ zn,             // 8 register-cached ||z||^2
    int l, int cbA, int cbB, float* best_v, int* best_i)
{
    ULL acc[4][8];
    #pragma unroll
    for (int p = 0; p < 4; ++p)
        #pragma unroll
        for (int c = 0; c < 8; ++c) acc[p][c] = 0ull;

    #pragma unroll 4
    for (int d = 0; d < DD; ++d) {
        ulonglong2 za = *(const ulonglong2*)(zb + d*68);       // (z0,z1),(z2,z3)
        ulonglong2 zc = *(const ulonglong2*)(zb + d*68 + 4);   // (z4,z5),(z6,z7)
        float4 ea = EA[d*32 + l];
        float4 eb = EB[d*32 + l];
        ULL e0 = dup2(ea.x), e1 = dup2(ea.y), e2 = dup2(ea.z), e3 = dup2(ea.w);
        ULL e4 = dup2(eb.x), e5 = dup2(eb.y), e6 = dup2(eb.z), e7 = dup2(eb.w);
        fma2(acc[0][0], za.x, e0); fma2(acc[1][0], za.y, e0);
        fma2(acc[2][0], zc.x, e0); fma2(acc[3][0], zc.y, e0);
        fma2(acc[0][1], za.x, e1); fma2(acc[1][1], za.y, e1);
        fma2(acc[2][1], zc.x, e1); fma2(acc[3][1], zc.y, e1);
        fma2(acc[0][2], za.x, e2); fma2(acc[1][2], za.y, e2);
        fma2(acc[2][2], zc.x, e2); fma2(acc[3][2], zc.y, e2);
        fma2(acc[0][3], za.x, e3); fma2(acc[1][3], za.y, e3);
        fma2(acc[2][3], zc.x, e3); fma2(acc[3][3], zc.y, e3);
        fma2(acc[0][4], za.x, e4); fma2(acc[1][4], za.y, e4);
        fma2(acc[2][4], zc.x, e4); fma2(acc[3][4], zc.y, e4);
        fma2(acc[0][5], za.x, e5); fma2(acc[1][5], za.y, e5);
        fma2(acc[2][5], zc.x, e5); fma2(acc[3][5], zc.y, e5);
        fma2(acc[0][6], za.x, e6); fma2(acc[1][6], za.y, e6);
        fma2(acc[2][6], zc.x, e6); fma2(acc[3][6], zc.y, e6);
        fma2(acc[0][7], za.x, e7); fma2(acc[1][7], za.y, e7);
        fma2(acc[2][7], zc.x, e7); fma2(acc[3][7], zc.y, e7);
    }

    float4 enA4 = *(const float4*)&EnA[4*l];
    float4 enB4 = *(const float4*)&EnB[4*l];
    const float enA_[4] = {enA4.x, enA4.y, enA4.z, enA4.w};
    const float enB_[4] = {enB4.x, enB4.y, enB4.z, enB4.w};
    #pragma unroll
    for (int p = 0; p < 4; ++p) {
        float zn0 = zn[2*p];
        float zn1 = zn[2*p + 1];
        #pragma unroll
        for (int c = 0; c < 4; ++c) {
            float2 dd = unpk(acc[p][c]);
            int code = cbA + 4*l + c;
            // (zn - 2*dot) + En ; fma(-2,dot,zn) == fsub(zn,2*dot) since 2*dot exact
            float v0 = __fadd_rn(__fmaf_rn(-2.f, dd.x, zn0), enA_[c]);
            float v1 = __fadd_rn(__fmaf_rn(-2.f, dd.y, zn1), enA_[c]);
            if (v0 < best_v[2*p])   { best_v[2*p]   = v0; best_i[2*p]   = code; }
            if (v1 < best_v[2*p+1]) { best_v[2*p+1] = v1; best_i[2*p+1] = code; }
        }
        #pragma unroll
        for (int c = 0; c < 4; ++c) {
            float2 dd = unpk(acc[p][4+c]);
            int code = cbB + 4*l + c;
            float v0 = __fadd_rn(__fmaf_rn(-2.f, dd.x, zn0), enB_[c]);
            float v1 = __fadd_rn(__fmaf_rn(-2.f, dd.y, zn1), enB_[c]);
            if (v0 < best_v[2*p])   { best_v[2*p]   = v0; best_i[2*p]   = code; }
            if (v1 < best_v[2*p+1]) { best_v[2*p+1] = v1; best_i[2*p+1] = code; }
        }
    }
}

__global__ __launch_bounds__(256, 2)
void qlayer_k1(const float* __restrict__ x,
               const float* __restrict__ W,
               const float* __restrict__ bias,
               const float* __restrict__ gamma,
               const float* __restrict__ beta,
               const float* __restrict__ bn_mean,
               const float* __restrict__ bn_var,
               const float* __restrict__ E,
               float* __restrict__ out)
{
    extern __shared__ char smraw[];
    float (*z_nd)[68]   = (float(*)[68])smraw;
    float (*x_nd)[68]   = (float(*)[68])(smraw + 17408);
    float (*W_sm)[DD]   = (float(*)[DD])(smraw + 34816);
    float (*att)[DD+1]  = (float(*)[DD+1])(smraw + 51200);
    float4* EB   = (float4*)(smraw + 17408);     // overlays x_nd + W_sm
    float4* EA   = (float4*)(smraw + 67840);     // dedicated
    float* EnA   = (float*)(smraw + 100608);
    float* EnB   = (float*)(smraw + 101120);
    float* znorm = (float*)(smraw + 101632);
    int*   lastf = (int*)(smraw + 101888);

    const int tid  = threadIdx.x;
    const int tok0 = blockIdx.x * TPB;
    const int s    = blockIdx.y;

    const float4* esrc  = g_Epack4 + (size_t)(s*NCHUNK) * 2048;
    const float*  ensrc = g_Enorm + s*KK;

    #define ISSUE(c, BUF, ENB) do {                                     \
        const float4* _src = esrc + (c)*2048;                           \
        _Pragma("unroll")                                               \
        for (int _i = tid; _i < 2048; _i += 256)                        \
            cp16(&(BUF)[_i], &_src[_i]);                                \
        if (tid < 32) cp16((float4*)(ENB) + tid,                        \
                           (const float4*)(ensrc + (c)*CHUNK) + tid);   \
        CP_COMMIT();                                                    \
    } while (0)

    // prefetch chunk 0 into dedicated EA (rides under proj+softmax)
    ISSUE(0, EA, EnA);

    // ---- load x tile transposed (non-dup); W in parallel ----
    {
        const int t = tid & 63, dg = tid >> 6;
        const float* xp = x + (size_t)(tok0 + t) * DD + dg * 16;
        #pragma unroll
        for (int j = 0; j < 4; ++j) {
            float4 v = *(const float4*)(xp + j * 4);
            int d = dg * 16 + j * 4;
            x_nd[d+0][t] = v.x; x_nd[d+1][t] = v.y;
            x_nd[d+2][t] = v.z; x_nd[d+3][t] = v.w;
        }
    }
    for (int i = tid; i < DD*DD; i += 256)
        ((float*)W_sm)[i] = W[s*DD*DD + i];
    __syncthreads();

    // ---- proj GEMM (f32x2 token-pairs): 4 tokens x 4 e per thread ----
    {
        const int ty = tid >> 4, tx = tid & 15;
        ULL acc[2][4];
        #pragma unroll
        for (int p = 0; p < 2; ++p)
            #pragma unroll
            for (int e = 0; e < 4; ++e) acc[p][e] = 0ull;
        #pragma unroll 8
        for (int d = 0; d < DD; ++d) {
            ulonglong2 xu = *(const ulonglong2*)&x_nd[d][ty*4];   // (x0,x1),(x2,x3)
            float4 wv = *(const float4*)&W_sm[d][tx*4];
            ULL w0 = dup2(wv.x), w1 = dup2(wv.y), w2 = dup2(wv.z), w3 = dup2(wv.w);
            fma2(acc[0][0], xu.x, w0); fma2(acc[1][0], xu.y, w0);
            fma2(acc[0][1], xu.x, w1); fma2(acc[1][1], xu.y, w1);
            fma2(acc[0][2], xu.x, w2); fma2(acc[1][2], xu.y, w2);
            fma2(acc[0][3], xu.x, w3); fma2(acc[1][3], xu.y, w3);
        }
        // BN, reference op order
        float4 bi4 = *(const float4*)&bias[s*DD + tx*4];
        float4 gm4 = *(const float4*)&gamma[s*DD + tx*4];
        float4 bt4 = *(const float4*)&beta[s*DD + tx*4];
        float4 mn4 = *(const float4*)&bn_mean[s*DD + tx*4];
        float4 vr4 = *(const float4*)&bn_var[s*DD + tx*4];
        const float bi_[4] = {bi4.x, bi4.y, bi4.z, bi4.w};
        const float gm_[4] = {gm4.x, gm4.y, gm4.z, gm4.w};
        const float bt_[4] = {bt4.x, bt4.y, bt4.z, bt4.w};
        const float mn_[4] = {mn4.x, mn4.y, mn4.z, mn4.w};
        float iv_[4];
        iv_[0] = 1.0f / sqrtf(__fadd_rn(vr4.x, 1e-3f));
        iv_[1] = 1.0f / sqrtf(__fadd_rn(vr4.y, 1e-3f));
        iv_[2] = 1.0f / sqrtf(__fadd_rn(vr4.z, 1e-3f));
        iv_[3] = 1.0f / sqrtf(__fadd_rn(vr4.w, 1e-3f));
        #pragma unroll
        for (int p = 0; p < 2; ++p) {
            #pragma unroll
            for (int e = 0; e < 4; ++e) {
                float2 pr = unpk(acc[p][e]);
                float pv = __fadd_rn(pr.x, bi_[e]);
                att[ty*4+2*p][tx*4+e] =
                    __fadd_rn(__fmul_rn(__fmul_rn(gm_[e], __fsub_rn(pv, mn_[e])), iv_[e]), bt_[e]);
                pv = __fadd_rn(pr.y, bi_[e]);
                att[ty*4+2*p+1][tx*4+e] =
                    __fadd_rn(__fmul_rn(__fmul_rn(gm_[e], __fsub_rn(pv, mn_[e])), iv_[e]), bt_[e]);
            }
        }
    }
    __syncthreads();

    // ---- softmax + z (4 threads/token), write z to smem (non-dup) + scratch ----
    {
        const int t = tid >> 2, q = tid & 3;
        float ev[16];
        float m = -INFINITY;
        #pragma unroll
        for (int j = 0; j < 16; ++j) { ev[j] = att[t][q*16 + j]; m = fmaxf(m, ev[j]); }
        m = fmaxf(m, __shfl_xor_sync(0xffffffffu, m, 1));
        m = fmaxf(m, __shfl_xor_sync(0xffffffffu, m, 2));
        float sum = 0.f;
        #pragma unroll
        for (int j = 0; j < 16; ++j) { ev[j] = expf(ev[j] - m); sum = __fadd_rn(sum, ev[j]); }
        sum = __fadd_rn(sum, __shfl_xor_sync(0xffffffffu, sum, 1));
        sum = __fadd_rn(sum, __shfl_xor_sync(0xffffffffu, sum, 2));
        float inv = __fdiv_rn(1.0f, sum);
        float zn = 0.f;
        float zv[16];
        #pragma unroll
        for (int j = 0; j < 16; ++j) {
            float a = __fmul_rn(ev[j], inv);
            float xx = x_nd[q*16 + j][t];
            float z = __fmul_rn(xx, a);
            zv[j] = z;
            z_nd[q*16 + j][t] = z;
            zn = __fadd_rn(zn, __fmul_rn(z, z));
        }
        float* zp = g_z + ((size_t)s*NTOK + tok0 + t) * DD + q*16;
        #pragma unroll
        for (int j4 = 0; j4 < 4; ++j4)
            *(float4*)(zp + 4*j4) = make_float4(zv[4*j4], zv[4*j4+1], zv[4*j4+2], zv[4*j4+3]);
        zn = __fadd_rn(zn, __shfl_xor_sync(0xffffffffu, zn, 1));
        zn = __fadd_rn(zn, __shfl_xor_sync(0xffffffffu, zn, 2));
        if (q == 0) znorm[t] = zn;
    }
    __syncthreads();    // z ready; x/W/att dead -> EB usable

    // ---- codebook distance: two pair-passes over (c0,c1) then (c2,c3) ----
    const int w = tid >> 5, l = tid & 31;
    const float* zb = &z_nd[0][w*8];
    float best_v[8]; int best_i[8];
    float znr[8];
    #pragma unroll
    for (int i = 0; i < 8; ++i) {
        best_v[i] = INFINITY; best_i[i] = 0x7fffffff;
        znr[i] = znorm[w*8 + i];                 // broadcast LDS, cached in regs
    }

    ISSUE(1, EB, EnB);
    CP_WAIT(0); __syncthreads();
    dist_pair(zb, EA, EB, EnA, EnB, znr, l, 0*CHUNK, 1*CHUNK, best_v, best_i);
    __syncthreads();

    ISSUE(2, EA, EnA);
    ISSUE(3, EB, EnB);
    CP_WAIT(0); __syncthreads();
    dist_pair(zb, EA, EB, EnA, EnB, znr, l, 2*CHUNK, 3*CHUNK, best_v, best_i);
    #undef ISSUE

    // ---- warp argmin reduction (first-occurrence => min index tie-break) ----
    #pragma unroll
    for (int i = 0; i < 8; ++i) {
        float v = best_v[i]; int bi = best_i[i];
        #pragma unroll
        for (int off = 16; off > 0; off >>= 1) {
            float ov = __shfl_xor_sync(0xffffffffu, v, off);
            int   oi = __shfl_xor_sync(0xffffffffu, bi, off);
            if (ov < v || (ov == v && oi < bi)) { v = ov; bi = oi; }
        }
        if (l == i)
            out[ZK_OFF + (size_t)s*NTOK + tok0 + w*8 + i] = (float)bi;
    }

    // ---- fused tail: 8th CTA of this tile reduces z_e / z_q (fixed s-order) ----
    __syncthreads();
    if (tid == 0) {
        __threadfence();
        int old = atomicAdd(&g_cnt[blockIdx.x], 1);
        *lastf = (old == SS-1);
    }
    __syncthreads();
    if (*lastf) {
        __threadfence();   // acquire: all 8 CTAs' g_z / zk writes visible
        const int t = tid >> 2, q = tid & 3;   // local token, quarter
        const int T = tok0 + t;
        float ae[16], aq[16];
        #pragma unroll
        for (int j = 0; j < 16; ++j) { ae[j] = 0.f; aq[j] = 0.f; }
        #pragma unroll
        for (int ss = 0; ss < SS; ++ss) {
            const float* zp = g_z + ((size_t)ss*NTOK + T) * DD + q*16;
            #pragma unroll
            for (int j4 = 0; j4 < 4; ++j4) {
                float4 v = *(const float4*)(zp + 4*j4);
                ae[4*j4+0] = __fadd_rn(ae[4*j4+0], v.x);
                ae[4*j4+1] = __fadd_rn(ae[4*j4+1], v.y);
                ae[4*j4+2] = __fadd_rn(ae[4*j4+2], v.z);
                ae[4*j4+3] = __fadd_rn(ae[4*j4+3], v.w);
            }
            const int k = (int)out[ZK_OFF + (size_t)ss*NTOK + T];
            const float* ep = E + ((size_t)ss*KK + k) * DD + q*16;
            #pragma unroll
            for (int j4 = 0; j4 < 4; ++j4) {
                float4 v = *(const float4*)(ep + 4*j4);
                aq[4*j4+0] = __fadd_rn(aq[4*j4+0], v.x);
                aq[4*j4+1] = __fadd_rn(aq[4*j4+1], v.y);
                aq[4*j4+2] = __fadd_rn(aq[4*j4+2], v.z);
                aq[4*j4+3] = __fadd_rn(aq[4*j4+3], v.w);
            }
        }
        float* oq = out + ZQ_OFF + (size_t)T * DD + q*16;
        float* oe = out + ZE_OFF + (size_t)T * DD + q*16;
        #pragma unroll
        for (int j4 = 0; j4 < 4; ++j4) {
            *(float4*)(oq + 4*j4) = make_float4(aq[4*j4], aq[4*j4+1], aq[4*j4+2], aq[4*j4+3]);
            *(float4*)(oe + 4*j4) = make_float4(ae[4*j4], ae[4*j4+1], ae[4*j4+2], ae[4*j4+3]);
        }
        if (tid == 0) g_cnt[blockIdx.x] = 0;   // reset for next graph replay
    }
}

extern "C" void kernel_launch(void* const* d_in, const int* in_sizes, int n_in,
                              void* d_out, int out_size)
{
    const float* x       = (const float*)d_in[0];
    const float* W       = (const float*)d_in[1];
    const float* b       = (const float*)d_in[2];
    const float* gamma   = (const float*)d_in[3];
    const float* beta    = (const float*)d_in[4];
    const float* bn_mean = (const float*)d_in[5];
    const float* bn_var  = (const float*)d_in[6];
    const float* E       = (const float*)d_in[7];
    float* out = (float*)d_out;

    prep_kernel<<<SS*NCHUNK*4 + 16, 256>>>(E);

    cudaFuncSetAttribute(qlayer_k1,
                         cudaFuncAttributeMaxDynamicSharedMemorySize, SMEM_BYTES);
    qlayer_k1<<<dim3(NTILE, SS), 256, SMEM_BYTES>>>(x, W, b, gamma, beta,
                                                    bn_mean, bn_var, E, out);
}

// round 16
// speedup vs baseline: 1.0709x; 1.0243x over previous
#include <cuda_runtime.h>
#include <math.h>

#define SS 8
#define DD 64
#define KK 512
#define NTOK 16384
#define TPB 64
#define CHUNK 128
#define NCHUNK 4
#define NTILE (NTOK/TPB)          // 256
#define ZQ_OFF 0
#define ZE_OFF (NTOK*DD)          // 1048576
#define ZK_OFF (2*NTOK*DD)        // 2097152

typedef unsigned long long ULL;

__device__ float g_Enorm[SS*KK];
// lane-quad pack: [s][c][d][q], float4 = codes (c*128+4q .. +3) at dim d
__device__ __align__(16) float4 g_Epack4[SS*NCHUNK*DD*32];
// per-slot z scratch: [s][token][d]  (32 MB)
__device__ __align__(16) float g_z[(size_t)SS*NTOK*DD];
// per-tile arrival counters (zero-init; winner resets -> invariant across replays)
__device__ int g_cnt[NTILE];

__device__ __forceinline__ void fma2(ULL& d, ULL a, ULL b) {
    asm("fma.rn.f32x2 %0, %1, %2, %3;" : "=l"(d) : "l"(a), "l"(b), "l"(d));
}
__device__ __forceinline__ float2 unpk(ULL v) {
    float lo, hi;
    asm("mov.b64 {%0,%1}, %2;" : "=f"(lo), "=f"(hi) : "l"(v));
    return make_float2(lo, hi);
}
__device__ __forceinline__ ULL dup2(float v) {
    ULL r; asm("mov.b64 %0, {%1, %1};" : "=l"(r) : "f"(v)); return r;
}
__device__ __forceinline__ void cp16(void* sdst, const void* gsrc) {
    unsigned sa = (unsigned)__cvta_generic_to_shared(sdst);
    asm volatile("cp.async.cg.shared.global [%0], [%1], 16;" :: "r"(sa), "l"(gsrc));
}
#define CP_COMMIT() asm volatile("cp.async.commit_group;")
#define CP_WAIT(n)  asm volatile("cp.async.wait_group %0;" :: "n"(n))

// ---- merged prep: blocks [0,128) transpose-pack; [128,144) norms ----
__global__ __launch_bounds__(256)
void prep_kernel(const float* __restrict__ E) {
    if (blockIdx.x < SS*NCHUNK*4) {
        __shared__ float tile[32][DD];        // 8 KB
        const int b   = blockIdx.x >> 2;      // chunk id: s*4 + c
        const int sub = blockIdx.x & 3;       // rows [sub*32, sub*32+32)
        const float* base = E + ((size_t)b * CHUNK + sub*32) * DD;
        for (int i = threadIdx.x; i < 32*DD/4; i += 256) {
            int row = i >> 4, f4 = i & 15;
            float4 v = *(const float4*)(base + row*DD + f4*4);
            tile[row][f4*4+0] = v.x; tile[row][f4*4+1] = v.y;
            tile[row][f4*4+2] = v.z; tile[row][f4*4+3] = v.w;
        }
        __syncthreads();
        for (int j = threadIdx.x; j < DD*8; j += 256) {
            int ql = j & 7, d = j >> 3;
            int lr = 4*ql;
            g_Epack4[b*2048 + d*32 + sub*8 + ql] =
                make_float4(tile[lr+0][d], tile[lr+1][d], tile[lr+2][d], tile[lr+3][d]);
        }
    } else {
        // norms: sequential d-order rounding (reference-matched)
        int row = (blockIdx.x - SS*NCHUNK*4) * 256 + threadIdx.x;   // < 4096
        const float* e = E + (size_t)row * DD;
        float4 v[16];
        #pragma unroll
        for (int j = 0; j < 16; ++j) v[j] = *(const float4*)(e + 4*j);
        float s = 0.f;
        #pragma unroll
        for (int j = 0; j < 16; ++j) {
            s = __fadd_rn(s, __fmul_rn(v[j].x, v[j].x));
            s = __fadd_rn(s, __fmul_rn(v[j].y, v[j].y));
            s = __fadd_rn(s, __fmul_rn(v[j].z, v[j].z));
            s = __fadd_rn(s, __fmul_rn(v[j].w, v[j].w));
        }
        g_Enorm[row] = s;
    }
}

// smem layout (102016 B), 2 CTAs/SM:
//  +0      z_nd  [64][68] = 17408   (live through dist)
//  +17408  x_nd  [64][68] = 17408 \  dead after softmax;
//  +34816  W_sm  [64][64] = 16384 /  EB (32768) overlays x_nd+W
//  +51200  att   [64][65] = 16640    (dead after softmax)
//  +67840  EA 32768 (dedicated; prefetched at kernel start)
//  +100608 EnA 512 | +101120 EnB 512 | +101632 znorm 256 | +101888 last_flag
#define SMEM_BYTES 102016

// two chunks per pass: codes cbA+4l..+3 (EA) and cbB+4l..+3 (EB); token-pair f32x2
__device__ __forceinline__ void dist_pair(
    const float* __restrict__ zb,             // &z_nd[0][w*8]
    const float4* __restrict__ EA, const float4* __restrict__ EB,
    const float* __restrict__ EnA, const float* __restrict__ EnB,
    const float* __restrict__ znorm,
    int w, int l, int cbA, int cbB, float* best_v, int* best_i)
{
    ULL acc[4][8];
    #pragma unroll
    for (int p = 0; p < 4; ++p)
        #pragma unroll
        for (int c = 0; c < 8; ++c) acc[p][c] = 0ull;

    #pragma unroll 4
    for (int d = 0; d < DD; ++d) {
        ulonglong2 za = *(const ulonglong2*)(zb + d*68);       // (z0,z1),(z2,z3)
        ulonglong2 zc = *(const ulonglong2*)(zb + d*68 + 4);   // (z4,z5),(z6,z7)
        float4 ea = EA[d*32 + l];
        float4 eb = EB[d*32 + l];
        ULL e0 = dup2(ea.x), e1 = dup2(ea.y), e2 = dup2(ea.z), e3 = dup2(ea.w);
        ULL e4 = dup2(eb.x), e5 = dup2(eb.y), e6 = dup2(eb.z), e7 = dup2(eb.w);
        fma2(acc[0][0], za.x, e0); fma2(acc[1][0], za.y, e0);
        fma2(acc[2][0], zc.x, e0); fma2(acc[3][0], zc.y, e0);
        fma2(acc[0][1], za.x, e1); fma2(acc[1][1], za.y, e1);
        fma2(acc[2][1], zc.x, e1); fma2(acc[3][1], zc.y, e1);
        fma2(acc[0][2], za.x, e2); fma2(acc[1][2], za.y, e2);
        fma2(acc[2][2], zc.x, e2); fma2(acc[3][2], zc.y, e2);
        fma2(acc[0][3], za.x, e3); fma2(acc[1][3], za.y, e3);
        fma2(acc[2][3], zc.x, e3); fma2(acc[3][3], zc.y, e3);
        fma2(acc[0][4], za.x, e4); fma2(acc[1][4], za.y, e4);
        fma2(acc[2][4], zc.x, e4); fma2(acc[3][4], zc.y, e4);
        fma2(acc[0][5], za.x, e5); fma2(acc[1][5], za.y, e5);
        fma2(acc[2][5], zc.x, e5); fma2(acc[3][5], zc.y, e5);
        fma2(acc[0][6], za.x, e6); fma2(acc[1][6], za.y, e6);
        fma2(acc[2][6], zc.x, e6); fma2(acc[3][6], zc.y, e6);
        fma2(acc[0][7], za.x, e7); fma2(acc[1][7], za.y, e7);
        fma2(acc[2][7], zc.x, e7); fma2(acc[3][7], zc.y, e7);
    }

    float4 enA4 = *(const float4*)&EnA[4*l];
    float4 enB4 = *(const float4*)&EnB[4*l];
    const float enA_[4] = {enA4.x, enA4.y, enA4.z, enA4.w};
    const float enB_[4] = {enB4.x, enB4.y, enB4.z, enB4.w};
    #pragma unroll
    for (int p = 0; p < 4; ++p) {
        float zn0 = znorm[w*8 + 2*p];
        float zn1 = znorm[w*8 + 2*p + 1];
        #pragma unroll
        for (int c = 0; c < 4; ++c) {
            float2 dd = unpk(acc[p][c]);
            int code = cbA + 4*l + c;
            // (zn - 2*dot) + En ; fma(-2,dot,zn) == fsub(zn,2*dot) since 2*dot exact
            float v0 = __fadd_rn(__fmaf_rn(-2.f, dd.x, zn0), enA_[c]);
            float v1 = __fadd_rn(__fmaf_rn(-2.f, dd.y, zn1), enA_[c]);
            if (v0 < best_v[2*p])   { best_v[2*p]   = v0; best_i[2*p]   = code; }
            if (v1 < best_v[2*p+1]) { best_v[2*p+1] = v1; best_i[2*p+1] = code; }
        }
        #pragma unroll
        for (int c = 0; c < 4; ++c) {
            float2 dd = unpk(acc[p][4+c]);
            int code = cbB + 4*l + c;
            float v0 = __fadd_rn(__fmaf_rn(-2.f, dd.x, zn0), enB_[c]);
            float v1 = __fadd_rn(__fmaf_rn(-2.f, dd.y, zn1), enB_[c]);
            if (v0 < best_v[2*p])   { best_v[2*p]   = v0; best_i[2*p]   = code; }
            if (v1 < best_v[2*p+1]) { best_v[2*p+1] = v1; best_i[2*p+1] = code; }
        }
    }
}

__global__ __launch_bounds__(256, 2)
void qlayer_k1(const float* __restrict__ x,
               const float* __restrict__ W,
               const float* __restrict__ bias,
               const float* __restrict__ gamma,
               const float* __restrict__ beta,
               const float* __restrict__ bn_mean,
               const float* __restrict__ bn_var,
               const float* __restrict__ E,
               float* __restrict__ out)
{
    extern __shared__ char smraw[];
    float (*z_nd)[68]   = (float(*)[68])smraw;
    float (*x_nd)[68]   = (float(*)[68])(smraw + 17408);
    float (*W_sm)[DD]   = (float(*)[DD])(smraw + 34816);
    float (*att)[DD+1]  = (float(*)[DD+1])(smraw + 51200);
    float4* EB   = (float4*)(smraw + 17408);     // overlays x_nd + W_sm
    float4* EA   = (float4*)(smraw + 67840);     // dedicated
    float* EnA   = (float*)(smraw + 100608);
    float* EnB   = (float*)(smraw + 101120);
    float* znorm = (float*)(smraw + 101632);
    int*   lastf = (int*)(smraw + 101888);

    const int tid  = threadIdx.x;
    const int tok0 = blockIdx.x * TPB;
    const int s    = blockIdx.y;

    const float4* esrc  = g_Epack4 + (size_t)(s*NCHUNK) * 2048;
    const float*  ensrc = g_Enorm + s*KK;

    #define ISSUE(c, BUF, ENB) do {                                     \
        const float4* _src = esrc + (c)*2048;                           \
        _Pragma("unroll")                                               \
        for (int _i = tid; _i < 2048; _i += 256)                        \
            cp16(&(BUF)[_i], &_src[_i]);                                \
        if (tid < 32) cp16((float4*)(ENB) + tid,                        \
                           (const float4*)(ensrc + (c)*CHUNK) + tid);   \
        CP_COMMIT();                                                    \
    } while (0)

    // prefetch chunk 0 into dedicated EA (rides under proj+softmax)
    ISSUE(0, EA, EnA);

    // ---- load x tile transposed (non-dup); W in parallel ----
    {
        const int t = tid & 63, dg = tid >> 6;
        const float* xp = x + (size_t)(tok0 + t) * DD + dg * 16;
        #pragma unroll
        for (int j = 0; j < 4; ++j) {
            float4 v = *(const float4*)(xp + j * 4);
            int d = dg * 16 + j * 4;
            x_nd[d+0][t] = v.x; x_nd[d+1][t] = v.y;
            x_nd[d+2][t] = v.z; x_nd[d+3][t] = v.w;
        }
    }
    for (int i = tid; i < DD*DD; i += 256)
        ((float*)W_sm)[i] = W[s*DD*DD + i];
    __syncthreads();

    // ---- proj GEMM (f32x2 token-pairs): 4 tokens x 4 e per thread ----
    {
        const int ty = tid >> 4, tx = tid & 15;
        ULL acc[2][4];
        #pragma unroll
        for (int p = 0; p < 2; ++p)
            #pragma unroll
            for (int e = 0; e < 4; ++e) acc[p][e] = 0ull;
        #pragma unroll 8
        for (int d = 0; d < DD; ++d) {
            ulonglong2 xu = *(const ulonglong2*)&x_nd[d][ty*4];   // (x0,x1),(x2,x3)
            float4 wv = *(const float4*)&W_sm[d][tx*4];
            ULL w0 = dup2(wv.x), w1 = dup2(wv.y), w2 = dup2(wv.z), w3 = dup2(wv.w);
            fma2(acc[0][0], xu.x, w0); fma2(acc[1][0], xu.y, w0);
            fma2(acc[0][1], xu.x, w1); fma2(acc[1][1], xu.y, w1);
            fma2(acc[0][2], xu.x, w2); fma2(acc[1][2], xu.y, w2);
            fma2(acc[0][3], xu.x, w3); fma2(acc[1][3], xu.y, w3);
        }
        // BN, reference op order
        float4 bi4 = *(const float4*)&bias[s*DD + tx*4];
        float4 gm4 = *(const float4*)&gamma[s*DD + tx*4];
        float4 bt4 = *(const float4*)&beta[s*DD + tx*4];
        float4 mn4 = *(const float4*)&bn_mean[s*DD + tx*4];
        float4 vr4 = *(const float4*)&bn_var[s*DD + tx*4];
        const float bi_[4] = {bi4.x, bi4.y, bi4.z, bi4.w};
        const float gm_[4] = {gm4.x, gm4.y, gm4.z, gm4.w};
        const float bt_[4] = {bt4.x, bt4.y, bt4.z, bt4.w};
        const float mn_[4] = {mn4.x, mn4.y, mn4.z, mn4.w};
        float iv_[4];
        iv_[0] = 1.0f / sqrtf(__fadd_rn(vr4.x, 1e-3f));
        iv_[1] = 1.0f / sqrtf(__fadd_rn(vr4.y, 1e-3f));
        iv_[2] = 1.0f / sqrtf(__fadd_rn(vr4.z, 1e-3f));
        iv_[3] = 1.0f / sqrtf(__fadd_rn(vr4.w, 1e-3f));
        #pragma unroll
        for (int p = 0; p < 2; ++p) {
            #pragma unroll
            for (int e = 0; e < 4; ++e) {
                float2 pr = unpk(acc[p][e]);
                float pv = __fadd_rn(pr.x, bi_[e]);
                att[ty*4+2*p][tx*4+e] =
                    __fadd_rn(__fmul_rn(__fmul_rn(gm_[e], __fsub_rn(pv, mn_[e])), iv_[e]), bt_[e]);
                pv = __fadd_rn(pr.y, bi_[e]);
                att[ty*4+2*p+1][tx*4+e] =
                    __fadd_rn(__fmul_rn(__fmul_rn(gm_[e], __fsub_rn(pv, mn_[e])), iv_[e]), bt_[e]);
            }
        }
    }
    __syncthreads();

    // ---- softmax + z (4 threads/token), write z to smem (non-dup) + scratch ----
    {
        const int t = tid >> 2, q = tid & 3;
        float ev[16];
        float m = -INFINITY;
        #pragma unroll
        for (int j = 0; j < 16; ++j) { ev[j] = att[t][q*16 + j]; m = fmaxf(m, ev[j]); }
        m = fmaxf(m, __shfl_xor_sync(0xffffffffu, m, 1));
        m = fmaxf(m, __shfl_xor_sync(0xffffffffu, m, 2));
        float sum = 0.f;
        #pragma unroll
        for (int j = 0; j < 16; ++j) { ev[j] = expf(ev[j] - m); sum = __fadd_rn(sum, ev[j]); }
        sum = __fadd_rn(sum, __shfl_xor_sync(0xffffffffu, sum, 1));
        sum = __fadd_rn(sum, __shfl_xor_sync(0xffffffffu, sum, 2));
        float inv = __fdiv_rn(1.0f, sum);
        float zn = 0.f;
        float zv[16];
        #pragma unroll
        for (int j = 0; j < 16; ++j) {
            float a = __fmul_rn(ev[j], inv);
            float xx = x_nd[q*16 + j][t];
            float z = __fmul_rn(xx, a);
            zv[j] = z;
            z_nd[q*16 + j][t] = z;
            zn = __fadd_rn(zn, __fmul_rn(z, z));
        }
        float* zp = g_z + ((size_t)s*NTOK + tok0 + t) * DD + q*16;
        #pragma unroll
        for (int j4 = 0; j4 < 4; ++j4)
            *(float4*)(zp + 4*j4) = make_float4(zv[4*j4], zv[4*j4+1], zv[4*j4+2], zv[4*j4+3]);
        zn = __fadd_rn(zn, __shfl_xor_sync(0xffffffffu, zn, 1));
        zn = __fadd_rn(zn, __shfl_xor_sync(0xffffffffu, zn, 2));
        if (q == 0) znorm[t] = zn;
    }
    __syncthreads();    // z ready; x/W/att dead -> EB usable

    // ---- codebook distance: two pair-passes over (c0,c1) then (c2,c3) ----
    const int w = tid >> 5, l = tid & 31;
    const float* zb = &z_nd[0][w*8];
    float best_v[8]; int best_i[8];
    #pragma unroll
    for (int i = 0; i < 8; ++i) { best_v[i] = INFINITY; best_i[i] = 0x7fffffff; }

    ISSUE(1, EB, EnB);
    CP_WAIT(0); __syncthreads();
    dist_pair(zb, EA, EB, EnA, EnB, znorm, w, l, 0*CHUNK, 1*CHUNK, best_v, best_i);
    __syncthreads();

    ISSUE(2, EA, EnA);
    ISSUE(3, EB, EnB);
    CP_WAIT(0); __syncthreads();
    dist_pair(zb, EA, EB, EnA, EnB, znorm, w, l, 2*CHUNK, 3*CHUNK, best_v, best_i);
    #undef ISSUE

    // ---- warp argmin reduction (first-occurrence => min index tie-break) ----
    #pragma unroll
    for (int i = 0; i < 8; ++i) {
        float v = best_v[i]; int bi = best_i[i];
        #pragma unroll
        for (int off = 16; off > 0; off >>= 1) {
            float ov = __shfl_xor_sync(0xffffffffu, v, off);
            int   oi = __shfl_xor_sync(0xffffffffu, bi, off);
            if (ov < v || (ov == v && oi < bi)) { v = ov; bi = oi; }
        }
        if (l == i)
            out[ZK_OFF + (size_t)s*NTOK + tok0 + w*8 + i] = (float)bi;
    }

    // ---- fused tail: 8th CTA of this tile reduces z_e / z_q (fixed s-order) ----
    __syncthreads();
    if (tid == 0) {
        __threadfence();
        int old = atomicAdd(&g_cnt[blockIdx.x], 1);
        *lastf = (old == SS-1);
    }
    __syncthreads();
    if (*lastf) {
        __threadfence();   // acquire: all 8 CTAs' g_z / zk writes visible
        const int t = tid >> 2, q = tid & 3;   // local token, quarter
        const int T = tok0 + t;
        float ae[16], aq[16];
        #pragma unroll
        for (int j = 0; j < 16; ++j) { ae[j] = 0.f; aq[j] = 0.f; }
        #pragma unroll
        for (int ss = 0; ss < SS; ++ss) {
            const float* zp = g_z + ((size_t)ss*NTOK + T) * DD + q*16;
            #pragma unroll
            for (int j4 = 0; j4 < 4; ++j4) {
                float4 v = *(const float4*)(zp + 4*j4);
                ae[4*j4+0] = __fadd_rn(ae[4*j4+0], v.x);
                ae[4*j4+1] = __fadd_rn(ae[4*j4+1], v.y);
                ae[4*j4+2] = __fadd_rn(ae[4*j4+2], v.z);
                ae[4*j4+3] = __fadd_rn(ae[4*j4+3], v.w);
            }
            const int k = (int)out[ZK_OFF + (size_t)ss*NTOK + T];
            const float* ep = E + ((size_t)ss*KK + k) * DD + q*16;
            #pragma unroll
            for (int j4 = 0; j4 < 4; ++j4) {
                float4 v = *(const float4*)(ep + 4*j4);
                aq[4*j4+0] = __fadd_rn(aq[4*j4+0], v.x);
                aq[4*j4+1] = __fadd_rn(aq[4*j4+1], v.y);
                aq[4*j4+2] = __fadd_rn(aq[4*j4+2], v.z);
                aq[4*j4+3] = __fadd_rn(aq[4*j4+3], v.w);
            }
        }
        float* oq = out + ZQ_OFF + (size_t)T * DD + q*16;
        float* oe = out + ZE_OFF + (size_t)T * DD + q*16;
        #pragma unroll
        for (int j4 = 0; j4 < 4; ++j4) {
            *(float4*)(oq + 4*j4) = make_float4(aq[4*j4], aq[4*j4+1], aq[4*j4+2], aq[4*j4+3]);
            *(float4*)(oe + 4*j4) = make_float4(ae[4*j4], ae[4*j4+1], ae[4*j4+2], ae[4*j4+3]);
        }
        if (tid == 0) g_cnt[blockIdx.x] = 0;   // reset for next graph replay
    }
}

extern "C" void kernel_launch(void* const* d_in, const int* in_sizes, int n_in,
                              void* d_out, int out_size)
{
    const float* x       = (const float*)d_in[0];
    const float* W       = (const float*)d_in[1];
    const float* b       = (const float*)d_in[2];
    const float* gamma   = (const float*)d_in[3];
    const float* beta    = (const float*)d_in[4];
    const float* bn_mean = (const float*)d_in[5];
    const float* bn_var  = (const float*)d_in[6];
    const float* E       = (const float*)d_in[7];
    float* out = (float*)d_out;

    prep_kernel<<<SS*NCHUNK*4 + 16, 256>>>(E);

    cudaFuncSetAttribute(qlayer_k1,
                         cudaFuncAttributeMaxDynamicSharedMemorySize, SMEM_BYTES);
    qlayer_k1<<<dim3(NTILE, SS), 256, SMEM_BYTES>>>(x, W, b, gamma, beta,
                                                    bn_mean, bn_var, E, out);
}

// round 17
// speedup vs baseline: 1.0784x; 1.0070x over previous
#include <cuda_runtime.h>
#include <math.h>

#define SS 8
#define DD 64
#define KK 512
#define NTOK 16384
#define TPB 64
#define CHUNK 128
#define NCHUNK 4
#define NTILE (NTOK/TPB)          // 256
#define ZQ_OFF 0
#define ZE_OFF (NTOK*DD)          // 1048576
#define ZK_OFF (2*NTOK*DD)        // 2097152

typedef unsigned long long ULL;

__device__ float g_Enorm[SS*KK];
// lane-quad pack: [s][c][d][q], float4 = codes (c*128+4q .. +3) at dim d
__device__ __align__(16) float4 g_Epack4[SS*NCHUNK*DD*32];
// per-slot z scratch: [s][token][d]  (32 MB)
__device__ __align__(16) float g_z[(size_t)SS*NTOK*DD];
// per-tile arrival counters (zero-init; winner resets -> invariant across replays)
__device__ int g_cnt[NTILE];

__device__ __forceinline__ void fma2(ULL& d, ULL a, ULL b) {
    asm("fma.rn.f32x2 %0, %1, %2, %3;" : "=l"(d) : "l"(a), "l"(b), "l"(d));
}
__device__ __forceinline__ float2 unpk(ULL v) {
    float lo, hi;
    asm("mov.b64 {%0,%1}, %2;" : "=f"(lo), "=f"(hi) : "l"(v));
    return make_float2(lo, hi);
}
__device__ __forceinline__ ULL dup2(float v) {
    ULL r; asm("mov.b64 %0, {%1, %1};" : "=l"(r) : "f"(v)); return r;
}
__device__ __forceinline__ void cp16(void* sdst, const void* gsrc) {
    unsigned sa = (unsigned)__cvta_generic_to_shared(sdst);
    asm volatile("cp.async.cg.shared.global [%0], [%1], 16;" :: "r"(sa), "l"(gsrc));
}
#define CP_COMMIT() asm volatile("cp.async.commit_group;")
#define CP_WAIT(n)  asm volatile("cp.async.wait_group %0;" :: "n"(n))

// ---- merged prep: blocks [0,128) transpose-pack; [128,144) norms ----
__global__ __launch_bounds__(256)
void prep_kernel(const float* __restrict__ E) {
    if (blockIdx.x < SS*NCHUNK*4) {
        __shared__ float tile[32][DD];        // 8 KB
        const int b   = blockIdx.x >> 2;      // chunk id: s*4 + c
        const int sub = blockIdx.x & 3;       // rows [sub*32, sub*32+32)
        const float* base = E + ((size_t)b * CHUNK + sub*32) * DD;
        for (int i = threadIdx.x; i < 32*DD/4; i += 256) {
            int row = i >> 4, f4 = i & 15;
            float4 v = *(const float4*)(base + row*DD + f4*4);
            tile[row][f4*4+0] = v.x; tile[row][f4*4+1] = v.y;
            tile[row][f4*4+2] = v.z; tile[row][f4*4+3] = v.w;
        }
        __syncthreads();
        for (int j = threadIdx.x; j < DD*8; j += 256) {
            int ql = j & 7, d = j >> 3;
            int lr = 4*ql;
            g_Epack4[b*2048 + d*32 + sub*8 + ql] =
                make_float4(tile[lr+0][d], tile[lr+1][d], tile[lr+2][d], tile[lr+3][d]);
        }
    } else {
        // norms: sequential d-order rounding (reference-matched)
        int row = (blockIdx.x - SS*NCHUNK*4) * 256 + threadIdx.x;   // < 4096
        const float* e = E + (size_t)row * DD;
        float4 v[16];
        #pragma unroll
        for (int j = 0; j < 16; ++j) v[j] = *(const float4*)(e + 4*j);
        float s = 0.f;
        #pragma unroll
        for (int j = 0; j < 16; ++j) {
            s = __fadd_rn(s, __fmul_rn(v[j].x, v[j].x));
            s = __fadd_rn(s, __fmul_rn(v[j].y, v[j].y));
            s = __fadd_rn(s, __fmul_rn(v[j].z, v[j].z));
            s = __fadd_rn(s, __fmul_rn(v[j].w, v[j].w));
        }
        g_Enorm[row] = s;
    }
}

// smem layout (102016 B), 2 CTAs/SM:
//  +0      z_nd  [64][68] = 17408   (live through dist)
//  +17408  x_nd  [64][68] = 17408 \  dead after softmax;
//  +34816  W_sm  [64][64] = 16384 /  EB (32768) overlays x_nd+W
//  +51200  att   [64][65] = 16640    (dead after softmax)
//  +67840  EA 32768 (dedicated; prefetched at kernel start)
//  +100608 EnA 512 | +101120 EnB 512 | +101632 znorm 256 | +101888 last_flag
#define SMEM_BYTES 102016

// two chunks per pass: codes cbA+4l..+3 (EA) and cbB+4l..+3 (EB); token-pair f32x2
__device__ __forceinline__ void dist_pair(
    const float* __restrict__ zb,             // &z_nd[0][w*8]
    const float4* __restrict__ EA, const float4* __restrict__ EB,
    const float* __restrict__ EnA, const float* __restrict__ EnB,
    const float* __restrict__ znorm,
    int w, int l, int cbA, int cbB, float* best_v, int* best_i)
{
    ULL acc[4][8];
    #pragma unroll
    for (int p = 0; p < 4; ++p)
        #pragma unroll
        for (int c = 0; c < 8; ++c) acc[p][c] = 0ull;

    #pragma unroll 4
    for (int d = 0; d < DD; ++d) {
        ulonglong2 za = *(const ulonglong2*)(zb + d*68);       // (z0,z1),(z2,z3)
        ulonglong2 zc = *(const ulonglong2*)(zb + d*68 + 4);   // (z4,z5),(z6,z7)
        float4 ea = EA[d*32 + l];
        float4 eb = EB[d*32 + l];
        ULL e0 = dup2(ea.x), e1 = dup2(ea.y), e2 = dup2(ea.z), e3 = dup2(ea.w);
        ULL e4 = dup2(eb.x), e5 = dup2(eb.y), e6 = dup2(eb.z), e7 = dup2(eb.w);
        fma2(acc[0][0], za.x, e0); fma2(acc[1][0], za.y, e0);
        fma2(acc[2][0], zc.x, e0); fma2(acc[3][0], zc.y, e0);
        fma2(acc[0][1], za.x, e1); fma2(acc[1][1], za.y, e1);
        fma2(acc[2][1], zc.x, e1); fma2(acc[3][1], zc.y, e1);
        fma2(acc[0][2], za.x, e2); fma2(acc[1][2], za.y, e2);
        fma2(acc[2][2], zc.x, e2); fma2(acc[3][2], zc.y, e2);
        fma2(acc[0][3], za.x, e3); fma2(acc[1][3], za.y, e3);
        fma2(acc[2][3], zc.x, e3); fma2(acc[3][3], zc.y, e3);
        fma2(acc[0][4], za.x, e4); fma2(acc[1][4], za.y, e4);
        fma2(acc[2][4], zc.x, e4); fma2(acc[3][4], zc.y, e4);
        fma2(acc[0][5], za.x, e5); fma2(acc[1][5], za.y, e5);
        fma2(acc[2][5], zc.x, e5); fma2(acc[3][5], zc.y, e5);
        fma2(acc[0][6], za.x, e6); fma2(acc[1][6], za.y, e6);
        fma2(acc[2][6], zc.x, e6); fma2(acc[3][6], zc.y, e6);
        fma2(acc[0][7], za.x, e7); fma2(acc[1][7], za.y, e7);
        fma2(acc[2][7], zc.x, e7); fma2(acc[3][7], zc.y, e7);
    }

    float4 enA4 = *(const float4*)&EnA[4*l];
    float4 enB4 = *(const float4*)&EnB[4*l];
    const float enA_[4] = {enA4.x, enA4.y, enA4.z, enA4.w};
    const float enB_[4] = {enB4.x, enB4.y, enB4.z, enB4.w};
    #pragma unroll
    for (int p = 0; p < 4; ++p) {
        float zn0 = znorm[w*8 + 2*p];
        float zn1 = znorm[w*8 + 2*p + 1];
        #pragma unroll
        for (int c = 0; c < 4; ++c) {
            float2 dd = unpk(acc[p][c]);
            int code = cbA + 4*l + c;
            // (zn - 2*dot) + En ; fma(-2,dot,zn) == fsub(zn,2*dot) since 2*dot exact
            float v0 = __fadd_rn(__fmaf_rn(-2.f, dd.x, zn0), enA_[c]);
            float v1 = __fadd_rn(__fmaf_rn(-2.f, dd.y, zn1), enA_[c]);
            if (v0 < best_v[2*p])   { best_v[2*p]   = v0; best_i[2*p]   = code; }
            if (v1 < best_v[2*p+1]) { best_v[2*p+1] = v1; best_i[2*p+1] = code; }
        }
        #pragma unroll
        for (int c = 0; c < 4; ++c) {
            float2 dd = unpk(acc[p][4+c]);
            int code = cbB + 4*l + c;
            float v0 = __fadd_rn(__fmaf_rn(-2.f, dd.x, zn0), enB_[c]);
            float v1 = __fadd_rn(__fmaf_rn(-2.f, dd.y, zn1), enB_[c]);
            if (v0 < best_v[2*p])   { best_v[2*p]   = v0; best_i[2*p]   = code; }
            if (v1 < best_v[2*p+1]) { best_v[2*p+1] = v1; best_i[2*p+1] = code; }
        }
    }
}

__global__ __launch_bounds__(256, 2)
void qlayer_k1(const float* __restrict__ x,
               const float* __restrict__ W,
               const float* __restrict__ bias,
               const float* __restrict__ gamma,
               const float* __restrict__ beta,
               const float* __restrict__ bn_mean,
               const float* __restrict__ bn_var,
               const float* __restrict__ E,
               float* __restrict__ out)
{
    extern __shared__ char smraw[];
    float (*z_nd)[68]   = (float(*)[68])smraw;
    float (*x_nd)[68]   = (float(*)[68])(smraw + 17408);
    float (*W_sm)[DD]   = (float(*)[DD])(smraw + 34816);
    float (*att)[DD+1]  = (float(*)[DD+1])(smraw + 51200);
    float4* EB   = (float4*)(smraw + 17408);     // overlays x_nd + W_sm
    float4* EA   = (float4*)(smraw + 67840);     // dedicated
    float* EnA   = (float*)(smraw + 100608);
    float* EnB   = (float*)(smraw + 101120);
    float* znorm = (float*)(smraw + 101632);
    int*   lastf = (int*)(smraw + 101888);

    const int tid  = threadIdx.x;
    const int tok0 = blockIdx.x * TPB;
    const int s    = blockIdx.y;

    const float4* esrc  = g_Epack4 + (size_t)(s*NCHUNK) * 2048;
    const float*  ensrc = g_Enorm + s*KK;

    #define ISSUE(c, BUF, ENB) do {                                     \
        const float4* _src = esrc + (c)*2048;                           \
        _Pragma("unroll")                                               \
        for (int _i = tid; _i < 2048; _i += 256)                        \
            cp16(&(BUF)[_i], &_src[_i]);                                \
        if (tid < 32) cp16((float4*)(ENB) + tid,                        \
                           (const float4*)(ensrc + (c)*CHUNK) + tid);   \
        CP_COMMIT();                                                    \
    } while (0)

    // prefetch chunk 0 into dedicated EA (rides under proj+softmax)
    ISSUE(0, EA, EnA);

    // ---- load x tile transposed (non-dup); W in parallel ----
    {
        const int t = tid & 63, dg = tid >> 6;
        const float* xp = x + (size_t)(tok0 + t) * DD + dg * 16;
        #pragma unroll
        for (int j = 0; j < 4; ++j) {
            float4 v = *(const float4*)(xp + j * 4);
            int d = dg * 16 + j * 4;
            x_nd[d+0][t] = v.x; x_nd[d+1][t] = v.y;
            x_nd[d+2][t] = v.z; x_nd[d+3][t] = v.w;
        }
    }
    for (int i = tid; i < DD*DD; i += 256)
        ((float*)W_sm)[i] = W[s*DD*DD + i];
    __syncthreads();

    // ---- proj GEMM (f32x2 token-pairs): 4 tokens x 4 e per thread ----
    {
        const int ty = tid >> 4, tx = tid & 15;
        ULL acc[2][4];
        #pragma unroll
        for (int p = 0; p < 2; ++p)
            #pragma unroll
            for (int e = 0; e < 4; ++e) acc[p][e] = 0ull;
        #pragma unroll 8
        for (int d = 0; d < DD; ++d) {
            ulonglong2 xu = *(const ulonglong2*)&x_nd[d][ty*4];   // (x0,x1),(x2,x3)
            float4 wv = *(const float4*)&W_sm[d][tx*4];
            ULL w0 = dup2(wv.x), w1 = dup2(wv.y), w2 = dup2(wv.z), w3 = dup2(wv.w);
            fma2(acc[0][0], xu.x, w0); fma2(acc[1][0], xu.y, w0);
            fma2(acc[0][1], xu.x, w1); fma2(acc[1][1], xu.y, w1);
            fma2(acc[0][2], xu.x, w2); fma2(acc[1][2], xu.y, w2);
            fma2(acc[0][3], xu.x, w3); fma2(acc[1][3], xu.y, w3);
        }
        // BN, reference op order
        float4 bi4 = *(const float4*)&bias[s*DD + tx*4];
        float4 gm4 = *(const float4*)&gamma[s*DD + tx*4];
        float4 bt4 = *(const float4*)&beta[s*DD + tx*4];
        float4 mn4 = *(const float4*)&bn_mean[s*DD + tx*4];
        float4 vr4 = *(const float4*)&bn_var[s*DD + tx*4];
        const float bi_[4] = {bi4.x, bi4.y, bi4.z, bi4.w};
        const float gm_[4] = {gm4.x, gm4.y, gm4.z, gm4.w};
        const float bt_[4] = {bt4.x, bt4.y, bt4.z, bt4.w};
        const float mn_[4] = {mn4.x, mn4.y, mn4.z, mn4.w};
        float iv_[4];
        iv_[0] = 1.0f / sqrtf(__fadd_rn(vr4.x, 1e-3f));
        iv_[1] = 1.0f / sqrtf(__fadd_rn(vr4.y, 1e-3f));
        iv_[2] = 1.0f / sqrtf(__fadd_rn(vr4.z, 1e-3f));
        iv_[3] = 1.0f / sqrtf(__fadd_rn(vr4.w, 1e-3f));
        #pragma unroll
        for (int p = 0; p < 2; ++p) {
            #pragma unroll
            for (int e = 0; e < 4; ++e) {
                float2 pr = unpk(acc[p][e]);
                float pv = __fadd_rn(pr.x, bi_[e]);
                att[ty*4+2*p][tx*4+e] =
                    __fadd_rn(__fmul_rn(__fmul_rn(gm_[e], __fsub_rn(pv, mn_[e])), iv_[e]), bt_[e]);
                pv = __fadd_rn(pr.y, bi_[e]);
                att[ty*4+2*p+1][tx*4+e] =
                    __fadd_rn(__fmul_rn(__fmul_rn(gm_[e], __fsub_rn(pv, mn_[e])), iv_[e]), bt_[e]);
            }
        }
    }
    __syncthreads();

    // ---- softmax + z (4 threads/token), write z to smem (non-dup) + scratch ----
    {
        const int t = tid >> 2, q = tid & 3;
        float ev[16];
        float m = -INFINITY;
        #pragma unroll
        for (int j = 0; j < 16; ++j) { ev[j] = att[t][q*16 + j]; m = fmaxf(m, ev[j]); }
        m = fmaxf(m, __shfl_xor_sync(0xffffffffu, m, 1));
        m = fmaxf(m, __shfl_xor_sync(0xffffffffu, m, 2));
        float sum = 0.f;
        #pragma unroll
        for (int j = 0; j < 16; ++j) { ev[j] = __expf(ev[j] - m); sum = __fadd_rn(sum, ev[j]); }
        sum = __fadd_rn(sum, __shfl_xor_sync(0xffffffffu, sum, 1));
        sum = __fadd_rn(sum, __shfl_xor_sync(0xffffffffu, sum, 2));
        float inv = __fdiv_rn(1.0f, sum);
        float zn = 0.f;
        float zv[16];
        #pragma unroll
        for (int j = 0; j < 16; ++j) {
            float a = __fmul_rn(ev[j], inv);
            float xx = x_nd[q*16 + j][t];
            float z = __fmul_rn(xx, a);
            zv[j] = z;
            z_nd[q*16 + j][t] = z;
            zn = __fadd_rn(zn, __fmul_rn(z, z));
        }
        float* zp = g_z + ((size_t)s*NTOK + tok0 + t) * DD + q*16;
        #pragma unroll
        for (int j4 = 0; j4 < 4; ++j4)
            *(float4*)(zp + 4*j4) = make_float4(zv[4*j4], zv[4*j4+1], zv[4*j4+2], zv[4*j4+3]);
        zn = __fadd_rn(zn, __shfl_xor_sync(0xffffffffu, zn, 1));
        zn = __fadd_rn(zn, __shfl_xor_sync(0xffffffffu, zn, 2));
        if (q == 0) znorm[t] = zn;
    }
    __syncthreads();    // z ready; x/W/att dead -> EB usable

    // ---- codebook distance: two pair-passes over (c0,c1) then (c2,c3) ----
    const int w = tid >> 5, l = tid & 31;
    const float* zb = &z_nd[0][w*8];
    float best_v[8]; int best_i[8];
    #pragma unroll
    for (int i = 0; i < 8; ++i) { best_v[i] = INFINITY; best_i[i] = 0x7fffffff; }

    ISSUE(1, EB, EnB);
    CP_WAIT(0); __syncthreads();
    dist_pair(zb, EA, EB, EnA, EnB, znorm, w, l, 0*CHUNK, 1*CHUNK, best_v, best_i);
    __syncthreads();

    ISSUE(2, EA, EnA);
    ISSUE(3, EB, EnB);
    CP_WAIT(0); __syncthreads();
    dist_pair(zb, EA, EB, EnA, EnB, znorm, w, l, 2*CHUNK, 3*CHUNK, best_v, best_i);
    #undef ISSUE

    // ---- warp argmin reduction (first-occurrence => min index tie-break) ----
    #pragma unroll
    for (int i = 0; i < 8; ++i) {
        float v = best_v[i]; int bi = best_i[i];
        #pragma unroll
        for (int off = 16; off > 0; off >>= 1) {
            float ov = __shfl_xor_sync(0xffffffffu, v, off);
            int   oi = __shfl_xor_sync(0xffffffffu, bi, off);
            if (ov < v || (ov == v && oi < bi)) { v = ov; bi = oi; }
        }
        if (l == i)
            out[ZK_OFF + (size_t)s*NTOK + tok0 + w*8 + i] = (float)bi;
    }

    // ---- fused tail: 8th CTA of this tile reduces z_e / z_q (fixed s-order) ----
    __syncthreads();
    if (tid == 0) {
        __threadfence();
        int old = atomicAdd(&g_cnt[blockIdx.x], 1);
        *lastf = (old == SS-1);
    }
    __syncthreads();
    if (*lastf) {
        __threadfence();   // acquire: all 8 CTAs' g_z / zk writes visible
        const int t = tid >> 2, q = tid & 3;   // local token, quarter
        const int T = tok0 + t;
        float ae[16], aq[16];
        #pragma unroll
        for (int j = 0; j < 16; ++j) { ae[j] = 0.f; aq[j] = 0.f; }
        #pragma unroll
        for (int ss = 0; ss < SS; ++ss) {
            const float* zp = g_z + ((size_t)ss*NTOK + T) * DD + q*16;
            #pragma unroll
            for (int j4 = 0; j4 < 4; ++j4) {
                float4 v = *(const float4*)(zp + 4*j4);
                ae[4*j4+0] = __fadd_rn(ae[4*j4+0], v.x);
                ae[4*j4+1] = __fadd_rn(ae[4*j4+1], v.y);
                ae[4*j4+2] = __fadd_rn(ae[4*j4+2], v.z);
                ae[4*j4+3] = __fadd_rn(ae[4*j4+3], v.w);
            }
            const int k = (int)out[ZK_OFF + (size_t)ss*NTOK + T];
            const float* ep = E + ((size_t)ss*KK + k) * DD + q*16;
            #pragma unroll
            for (int j4 = 0; j4 < 4; ++j4) {
                float4 v = *(const float4*)(ep + 4*j4);
                aq[4*j4+0] = __fadd_rn(aq[4*j4+0], v.x);
                aq[4*j4+1] = __fadd_rn(aq[4*j4+1], v.y);
                aq[4*j4+2] = __fadd_rn(aq[4*j4+2], v.z);
                aq[4*j4+3] = __fadd_rn(aq[4*j4+3], v.w);
            }
        }
        float* oq = out + ZQ_OFF + (size_t)T * DD + q*16;
        float* oe = out + ZE_OFF + (size_t)T * DD + q*16;
        #pragma unroll
        for (int j4 = 0; j4 < 4; ++j4) {
            *(float4*)(oq + 4*j4) = make_float4(aq[4*j4], aq[4*j4+1], aq[4*j4+2], aq[4*j4+3]);
            *(float4*)(oe + 4*j4) = make_float4(ae[4*j4], ae[4*j4+1], ae[4*j4+2], ae[4*j4+3]);
        }
        if (tid == 0) g_cnt[blockIdx.x] = 0;   // reset for next graph replay
    }
}

extern "C" void kernel_launch(void* const* d_in, const int* in_sizes, int n_in,
                              void* d_out, int out_size)
{
    const float* x       = (const float*)d_in[0];
    const float* W       = (const float*)d_in[1];
    const float* b       = (const float*)d_in[2];
    const float* gamma   = (const float*)d_in[3];
    const float* beta    = (const float*)d_in[4];
    const float* bn_mean = (const float*)d_in[5];
    const float* bn_var  = (const float*)d_in[6];
    const float* E       = (const float*)d_in[7];
    float* out = (float*)d_out;

    prep_kernel<<<SS*NCHUNK*4 + 16, 256>>>(E);

    cudaFuncSetAttribute(qlayer_k1,
                         cudaFuncAttributeMaxDynamicSharedMemorySize, SMEM_BYTES);
    qlayer_k1<<<dim3(NTILE, SS), 256, SMEM_BYTES>>>(x, W, b, gamma, beta,
                                                    bn_mean, bn_var, E, out);
}